// round 3
// baseline (speedup 1.0000x reference)
#include <cuda_runtime.h>
#include <cstdint>
#include <cstddef>

#define NN 50000
#define DD 256
#define RR 8
#define EE 300000
#define CO (RR * DD + DD)   // 2304 output cols per layer GEMM
#define ROOTOFF (RR * DD)   // 2048

// Scratch (16B+ aligned: float4 loads and red.global.add.v4.f32).
__device__ __align__(256) float g_Y[(size_t)NN * CO];   // ~460.8 MB
__device__ __align__(256) float g_H[(size_t)NN * DD];   // ~51.2 MB
__device__ int g_idx64;                                  // 1 if edge arrays are int64

#define BM 128
#define BN 128
#define BK 16

// Detect edge index dtype: if the data is int64 (values < 2^31), every odd
// int32 word (the high half) is 0. With int32 data those words are random
// node ids — all-zero over 32 samples has probability ~(2e-5)^32 ~ 0.
__global__ void detect_kernel(const int* __restrict__ ei32)
{
    int allzero = 1;
    for (int i = 1; i < 64; i += 2)
        if (ei32[i] != 0) allzero = 0;
    g_idx64 = allzero;
}

// C[m, c] for c in [by*128, by*128+128): one 256-col group per 2 col-tiles.
// group<8 -> weights[l][group]; group==8 -> root (add bias).
__global__ __launch_bounds__(256, 2)
void gemm_kernel(const float* __restrict__ Ain,
                 const float* __restrict__ Wl,
                 const float* __restrict__ rootl,
                 const float* __restrict__ biasl,
                 int a_from_gH)
{
    __shared__ float As[BK][BM];
    __shared__ float Bs[BK][BN];

    const float* A = a_from_gH ? g_H : Ain;

    const int m0 = blockIdx.x * BM;
    const int by = blockIdx.y;
    const int group = by >> 1;                 // 0..8
    const int e0 = (by & 1) * BN;              // 0 or 128 within group
    const float* Bbase = (group < RR) ? (Wl + (size_t)group * DD * DD) : rootl;

    const int t = threadIdx.x;
    const int tx = t & 15, ty = t >> 4;
    const int tm0 = ty * 8, tn0 = tx * 8;

    unsigned long long acc[8][4];
#pragma unroll
    for (int i = 0; i < 8; i++)
#pragma unroll
        for (int j = 0; j < 4; j++) acc[i][j] = 0ull;

    for (int kt = 0; kt < DD / BK; kt++) {
        // A tile: 128 rows x 16 k = 512 float4, 2 per thread, stored transposed As[k][m]
#pragma unroll
        for (int i = 0; i < 2; i++) {
            int f = t + i * 256;
            int row = f >> 2;              // 0..127
            int kc = (f & 3) * 4;          // 0,4,8,12
            float4 v = make_float4(0.f, 0.f, 0.f, 0.f);
            int gr = m0 + row;
            if (gr < NN)
                v = *(const float4*)(A + (size_t)gr * DD + kt * BK + kc);
            As[kc + 0][row] = v.x;
            As[kc + 1][row] = v.y;
            As[kc + 2][row] = v.z;
            As[kc + 3][row] = v.w;
        }
        // B tile: 16 k x 128 e = 512 float4, 2 per thread
#pragma unroll
        for (int i = 0; i < 2; i++) {
            int f = t + i * 256;
            int d = f >> 5;                // 0..15
            int e = (f & 31) * 4;
            float4 v = *(const float4*)(Bbase + (size_t)(kt * BK + d) * DD + e0 + e);
            *(float4*)&Bs[d][e] = v;
        }
        __syncthreads();

#pragma unroll
        for (int k = 0; k < BK; k++) {
            float4 a0 = *(const float4*)&As[k][tm0];
            float4 a1 = *(const float4*)&As[k][tm0 + 4];
            float4 b0 = *(const float4*)&Bs[k][tn0];
            float4 b1 = *(const float4*)&Bs[k][tn0 + 4];
            unsigned long long bp[4];
            asm("mov.b64 %0, {%1, %2};" : "=l"(bp[0]) : "f"(b0.x), "f"(b0.y));
            asm("mov.b64 %0, {%1, %2};" : "=l"(bp[1]) : "f"(b0.z), "f"(b0.w));
            asm("mov.b64 %0, {%1, %2};" : "=l"(bp[2]) : "f"(b1.x), "f"(b1.y));
            asm("mov.b64 %0, {%1, %2};" : "=l"(bp[3]) : "f"(b1.z), "f"(b1.w));
            float av[8] = { a0.x, a0.y, a0.z, a0.w, a1.x, a1.y, a1.z, a1.w };
#pragma unroll
            for (int i = 0; i < 8; i++) {
                unsigned long long ad;
                asm("mov.b64 %0, {%1, %1};" : "=l"(ad) : "f"(av[i]));
#pragma unroll
                for (int j = 0; j < 4; j++) {
                    // packed fp32 pair FMA: 2x fp32 throughput on sm_103a
                    asm("fma.rn.f32x2 %0, %1, %2, %0;"
                        : "+l"(acc[i][j]) : "l"(ad), "l"(bp[j]));
                }
            }
        }
        __syncthreads();
    }

    const int c0 = by * BN + tn0;             // global output column base
    const bool isroot = (group == RR);
#pragma unroll
    for (int i = 0; i < 8; i++) {
        int row = m0 + tm0 + i;
        if (row < NN) {
            float* yr = g_Y + (size_t)row * CO + c0;
#pragma unroll
            for (int j = 0; j < 4; j++) {
                float2 v = *(float2*)&acc[i][j];
                if (isroot) {
                    v.x += biasl[c0 + 2 * j - ROOTOFF];
                    v.y += biasl[c0 + 2 * j + 1 - ROOTOFF];
                }
                *(float2*)(yr + 2 * j) = v;
            }
        }
    }
}

// One warp per edge: gather Y[src, rel*256 : +256], vector-atomic into Y[dst, 2048 : +256]
__global__ void scatter_kernel(const void* __restrict__ ei,
                               const void* __restrict__ et)
{
    int w = (blockIdx.x * blockDim.x + threadIdx.x) >> 5;
    int lane = threadIdx.x & 31;
    if (w >= EE) return;
    long long src, dst, rel;
    if (g_idx64) {
        src = ((const long long*)ei)[w];
        dst = ((const long long*)ei)[EE + w];
        rel = ((const long long*)et)[w];
    } else {
        src = ((const int*)ei)[w];
        dst = ((const int*)ei)[EE + w];
        rel = ((const int*)et)[w];
    }
    if ((unsigned long long)src >= NN || (unsigned long long)dst >= NN ||
        (unsigned long long)rel >= RR) return;
    const float4* srow = (const float4*)(g_Y + (size_t)src * CO + rel * DD);
    float* drow = g_Y + (size_t)dst * CO + ROOTOFF;
#pragma unroll
    for (int i = 0; i < 2; i++) {
        float4 v = srow[lane + 32 * i];
        float* p = drow + (size_t)(lane + 32 * i) * 4;
        asm volatile("red.global.add.v4.f32 [%0], {%1, %2, %3, %4};"
                     :: "l"(p), "f"(v.x), "f"(v.y), "f"(v.z), "f"(v.w)
                     : "memory");
    }
}

// Read root section of Y, apply relu (write g_H) or sigmoid (write out).
__global__ void act_kernel(float* __restrict__ out, int sigmoid_mode)
{
    int idx = blockIdx.x * blockDim.x + threadIdx.x;   // over NN * 64 float4s
    if (idx >= NN * (DD / 4)) return;
    int n = idx / (DD / 4);
    int j = idx % (DD / 4);
    float4 v = *(const float4*)(g_Y + (size_t)n * CO + ROOTOFF + j * 4);
    float4 r;
    if (sigmoid_mode) {
        r.x = 1.f / (1.f + expf(-v.x));
        r.y = 1.f / (1.f + expf(-v.y));
        r.z = 1.f / (1.f + expf(-v.z));
        r.w = 1.f / (1.f + expf(-v.w));
        *(float4*)(out + (size_t)idx * 4) = r;
    } else {
        r.x = fmaxf(v.x, 0.f);
        r.y = fmaxf(v.y, 0.f);
        r.z = fmaxf(v.z, 0.f);
        r.w = fmaxf(v.w, 0.f);
        *(float4*)(g_H + (size_t)idx * 4) = r;
    }
}

extern "C" void kernel_launch(void* const* d_in, const int* in_sizes, int n_in,
                              void* d_out, int out_size)
{
    const float* x       = (const float*)d_in[0];     // [50000, 256]
    const float* weights = (const float*)d_in[1];     // [3, 8, 256, 256]
    const float* roots   = (const float*)d_in[2];     // [3, 256, 256]
    const float* biases  = (const float*)d_in[3];     // [3, 256]
    const void*  ei      = d_in[4];                   // [2, 300000] int32 or int64
    const void*  et      = d_in[5];                   // [300000]    int32 or int64

    dim3 ggrid((NN + BM - 1) / BM, CO / BN);   // 391 x 18
    int sc_blocks = (EE * 32 + 255) / 256;     // 8 edges (warps) per block
    int act_blocks = (NN * (DD / 4) + 255) / 256;

    detect_kernel<<<1, 1>>>((const int*)ei);

    for (int l = 0; l < 3; l++) {
        gemm_kernel<<<ggrid, 256>>>(x,
                                    weights + (size_t)l * RR * DD * DD,
                                    roots + (size_t)l * DD * DD,
                                    biases + (size_t)l * DD,
                                    l > 0 ? 1 : 0);
        scatter_kernel<<<sc_blocks, 256>>>(ei, et);
        act_kernel<<<act_blocks, 256>>>((float*)d_out, l == 2 ? 1 : 0);
    }
}

// round 5
// speedup vs baseline: 1.7862x; 1.7862x over previous
#include <cuda_runtime.h>
#include <cuda_bf16.h>
#include <cstdint>
#include <cstddef>

#define NN 50000
#define DD 256
#define RR 8
#define EE 300000
#define CO 2304
#define ROOTOFF 2048
#define GG 9            // 8 relations + root

// ---------------- device scratch ----------------
__device__ __align__(256) float g_Y[(size_t)NN * CO];                     // ~461 MB
__device__ __align__(256) __nv_bfloat16 g_Ahi[(size_t)NN * DD];
__device__ __align__(256) __nv_bfloat16 g_Alo[(size_t)NN * DD];
__device__ __align__(256) __nv_bfloat16 g_Whi[(size_t)3 * GG * DD * DD];  // [l][g][n][k]
__device__ __align__(256) __nv_bfloat16 g_Wlo[(size_t)3 * GG * DD * DD];
__device__ int g_idx64;

// ---------------- small kernels ----------------
__global__ void detect_kernel(const int* __restrict__ ei32) {
    int allzero = 1;
    for (int i = 1; i < 64; i += 2)
        if (ei32[i] != 0) allzero = 0;
    g_idx64 = allzero;
}

// Split-convert weights+roots, transposed to [l][g][n][k] (k contiguous).
__global__ void conv_w_kernel(const float* __restrict__ weights, const float* __restrict__ roots) {
    size_t i = (size_t)blockIdx.x * 256 + threadIdx.x;
    if (i >= (size_t)3 * GG * DD * DD) return;
    int k = (int)(i & 255);
    int n = (int)((i >> 8) & 255);
    int lg = (int)(i >> 16);
    int l = lg / GG, g = lg % GG;
    float w = (g < 8) ? weights[(((size_t)(l * 8 + g)) * DD + k) * DD + n]
                      : roots[((size_t)l * DD + k) * DD + n];
    __nv_bfloat16 hi = __float2bfloat16(w);
    __nv_bfloat16 lo = __float2bfloat16(w - __bfloat162float(hi));
    g_Whi[i] = hi;
    g_Wlo[i] = lo;
}

__global__ void conv_x_kernel(const float* __restrict__ x) {
    int i = blockIdx.x * 256 + threadIdx.x;
    if (i >= NN * DD) return;
    float a = x[i];
    __nv_bfloat16 hi = __float2bfloat16(a);
    g_Ahi[i] = hi;
    g_Alo[i] = __float2bfloat16(a - __bfloat162float(hi));
}

// relu(g_Y root section) -> split bf16 hi/lo for next layer's A
__global__ void act_split_kernel() {
    int i = blockIdx.x * 256 + threadIdx.x;
    if (i >= NN * DD) return;
    int n = i >> 8, j = i & 255;
    float v = fmaxf(g_Y[(size_t)n * CO + ROOTOFF + j], 0.f);
    __nv_bfloat16 hi = __float2bfloat16(v);
    g_Ahi[i] = hi;
    g_Alo[i] = __float2bfloat16(v - __bfloat162float(hi));
}

__global__ void act_final_kernel(float* __restrict__ out) {
    int idx = blockIdx.x * 256 + threadIdx.x;
    if (idx >= NN * (DD / 4)) return;
    int n = idx / (DD / 4);
    int j = idx % (DD / 4);
    float4 v = *(const float4*)(g_Y + (size_t)n * CO + ROOTOFF + j * 4);
    float4 r;
    r.x = 1.f / (1.f + expf(-v.x));
    r.y = 1.f / (1.f + expf(-v.y));
    r.z = 1.f / (1.f + expf(-v.z));
    r.w = 1.f / (1.f + expf(-v.w));
    *(float4*)(out + (size_t)idx * 4) = r;
}

// ---------------- HMMA (mma.sync) GEMM ----------------
// C[50000, 2304] = A @ Bcat via 3-term bf16 split, m16n8k16 bf16 MMA.
#define BM 128
#define BN 128
#define BK 32
#define STAGES 3
#define LDS_B 80                       // padded smem row stride in bytes (conflict-free)
#define ARR (128 * LDS_B)              // 10240 bytes per 128x32 bf16 array
#define OFF_AHI 0
#define OFF_ALO ARR
#define OFF_BHI (2 * ARR)
#define OFF_BLO (3 * ARR)
#define STAGE_BYTES (4 * ARR)          // 40960
#define SMEM_TOTAL (STAGES * STAGE_BYTES)  // 122880

#define CP_ASYNC16(dst, src) \
    asm volatile("cp.async.cg.shared.global [%0], [%1], 16;" :: "r"(dst), "l"(src) : "memory")
#define CP_COMMIT() asm volatile("cp.async.commit_group;" ::: "memory")
#define CP_WAIT2()  asm volatile("cp.async.wait_group 2;" ::: "memory")

__device__ __forceinline__ uint32_t smem_u32(const void* p) {
    uint32_t a;
    asm("{ .reg .u64 t; cvta.to.shared.u64 t, %1; cvt.u32.u64 %0, t; }" : "=r"(a) : "l"(p));
    return a;
}

__device__ __forceinline__ void mma16816(float* d, const uint32_t* a, const uint32_t* b) {
    asm volatile(
        "mma.sync.aligned.m16n8k16.row.col.f32.bf16.bf16.f32 "
        "{%0,%1,%2,%3}, {%4,%5,%6,%7}, {%8,%9}, {%0,%1,%2,%3};"
        : "+f"(d[0]), "+f"(d[1]), "+f"(d[2]), "+f"(d[3])
        : "r"(a[0]), "r"(a[1]), "r"(a[2]), "r"(a[3]), "r"(b[0]), "r"(b[1]));
}

__global__ __launch_bounds__(256, 1)
void gemm_kernel(const float* __restrict__ bias, int lay) {
    extern __shared__ char smem[];
    const uint32_t sb = smem_u32(smem);
    const int t = threadIdx.x;
    const int wid = t >> 5, lane = t & 31;
    const int g = lane >> 2, t4 = lane & 3;
    const int m0 = blockIdx.x * BM;
    const int nt = blockIdx.y;
    const int warp_m = wid & 3, warp_n = wid >> 2;   // 4 x 2 warp grid

    const int gidx = nt >> 1, nh = nt & 1;
    const __nv_bfloat16* Bh = g_Whi + ((size_t)(lay * GG + gidx) * DD + nh * 128) * DD;
    const __nv_bfloat16* Bl = g_Wlo + ((size_t)(lay * GG + gidx) * DD + nh * 128) * DD;

    float acc[2][8][4];
#pragma unroll
    for (int mi = 0; mi < 2; mi++)
#pragma unroll
        for (int nj = 0; nj < 8; nj++)
#pragma unroll
            for (int q = 0; q < 4; q++) acc[mi][nj][q] = 0.f;

    // Per-thread chunk assignment: 512 16B-chunks per 128x32 array, 2 per thread.
    auto load_stage = [&](int kt, int stage) {
        const int k0 = kt * BK;
        const uint32_t stb = sb + stage * STAGE_BYTES;
#pragma unroll
        for (int i = 0; i < 2; i++) {
            int c = t + i * 256;                 // 0..511
            int row = c >> 2;
            int col8 = (c & 3) * 8;              // bf16 col of 16B chunk
            uint32_t doff = (uint32_t)(row * LDS_B + col8 * 2);
            int gr = m0 + row;
            if (gr < NN) {
                CP_ASYNC16(stb + OFF_AHI + doff, g_Ahi + (size_t)gr * DD + k0 + col8);
                CP_ASYNC16(stb + OFF_ALO + doff, g_Alo + (size_t)gr * DD + k0 + col8);
            } else {
                *(uint4*)(smem + stage * STAGE_BYTES + OFF_AHI + doff) = make_uint4(0, 0, 0, 0);
                *(uint4*)(smem + stage * STAGE_BYTES + OFF_ALO + doff) = make_uint4(0, 0, 0, 0);
            }
            CP_ASYNC16(stb + OFF_BHI + doff, Bh + (size_t)row * DD + k0 + col8);
            CP_ASYNC16(stb + OFF_BLO + doff, Bl + (size_t)row * DD + k0 + col8);
        }
    };

#pragma unroll
    for (int s = 0; s < STAGES; s++) {
        load_stage(s, s);
        CP_COMMIT();
    }

    const int NKT = DD / BK;   // 8
    for (int kt = 0; kt < NKT; kt++) {
        CP_WAIT2();
        __syncthreads();
        const int stage = kt % STAGES;
        const char* stp = smem + stage * STAGE_BYTES;

#pragma unroll
        for (int h = 0; h < 2; h++) {            // two k16 halves of BK=32
            uint32_t ahi[2][4], alo[2][4], bhi[8][2], blo[8][2];
#pragma unroll
            for (int mi = 0; mi < 2; mi++) {
                int arow = warp_m * 32 + mi * 16 + g;
                const char* pa = stp + arow * LDS_B + (h * 16 + t4 * 2) * 2;
                ahi[mi][0] = *(const uint32_t*)(pa + OFF_AHI);
                ahi[mi][1] = *(const uint32_t*)(pa + OFF_AHI + 8 * LDS_B);
                ahi[mi][2] = *(const uint32_t*)(pa + OFF_AHI + 16);
                ahi[mi][3] = *(const uint32_t*)(pa + OFF_AHI + 8 * LDS_B + 16);
                alo[mi][0] = *(const uint32_t*)(pa + OFF_ALO);
                alo[mi][1] = *(const uint32_t*)(pa + OFF_ALO + 8 * LDS_B);
                alo[mi][2] = *(const uint32_t*)(pa + OFF_ALO + 16);
                alo[mi][3] = *(const uint32_t*)(pa + OFF_ALO + 8 * LDS_B + 16);
            }
#pragma unroll
            for (int nj = 0; nj < 8; nj++) {
                int brow = warp_n * 64 + nj * 8 + g;
                const char* pb = stp + brow * LDS_B + (h * 16 + t4 * 2) * 2;
                bhi[nj][0] = *(const uint32_t*)(pb + OFF_BHI);
                bhi[nj][1] = *(const uint32_t*)(pb + OFF_BHI + 16);
                blo[nj][0] = *(const uint32_t*)(pb + OFF_BLO);
                blo[nj][1] = *(const uint32_t*)(pb + OFF_BLO + 16);
            }
#pragma unroll
            for (int mi = 0; mi < 2; mi++)
#pragma unroll
                for (int nj = 0; nj < 8; nj++) {
                    mma16816(acc[mi][nj], ahi[mi], bhi[nj]);
                    mma16816(acc[mi][nj], ahi[mi], blo[nj]);
                    mma16816(acc[mi][nj], alo[mi], bhi[nj]);
                }
        }
        __syncthreads();
        if (kt + STAGES < NKT) load_stage(kt + STAGES, (kt + STAGES) % STAGES);
        CP_COMMIT();                              // keep group count uniform
    }

    // Epilogue: write C (+bias for root tiles) straight to g_Y.
    const bool isroot = (nt >= 16);
#pragma unroll
    for (int mi = 0; mi < 2; mi++) {
        int row0 = m0 + warp_m * 32 + mi * 16 + g;
#pragma unroll
        for (int nj = 0; nj < 8; nj++) {
            int col = nt * BN + warp_n * 64 + nj * 8 + t4 * 2;
            float b0 = 0.f, b1 = 0.f;
            if (isroot) {
                b0 = bias[col - ROOTOFF];
                b1 = bias[col + 1 - ROOTOFF];
            }
            if (row0 < NN) {
                float2 v = make_float2(acc[mi][nj][0] + b0, acc[mi][nj][1] + b1);
                *(float2*)(g_Y + (size_t)row0 * CO + col) = v;
            }
            if (row0 + 8 < NN) {
                float2 v = make_float2(acc[mi][nj][2] + b0, acc[mi][nj][3] + b1);
                *(float2*)(g_Y + (size_t)(row0 + 8) * CO + col) = v;
            }
        }
    }
}

// ---------------- scatter ----------------
__global__ void scatter_kernel(const void* __restrict__ ei, const void* __restrict__ et) {
    int w = (blockIdx.x * blockDim.x + threadIdx.x) >> 5;
    int lane = threadIdx.x & 31;
    if (w >= EE) return;
    long long src, dst, rel;
    if (g_idx64) {
        src = ((const long long*)ei)[w];
        dst = ((const long long*)ei)[EE + w];
        rel = ((const long long*)et)[w];
    } else {
        src = ((const int*)ei)[w];
        dst = ((const int*)ei)[EE + w];
        rel = ((const int*)et)[w];
    }
    if ((unsigned long long)src >= NN || (unsigned long long)dst >= NN ||
        (unsigned long long)rel >= RR) return;
    const float4* srow = (const float4*)(g_Y + (size_t)src * CO + rel * DD);
    float* drow = g_Y + (size_t)dst * CO + ROOTOFF;
#pragma unroll
    for (int i = 0; i < 2; i++) {
        float4 v = srow[lane + 32 * i];
        float* p = drow + (size_t)(lane + 32 * i) * 4;
        asm volatile("red.global.add.v4.f32 [%0], {%1, %2, %3, %4};"
                     :: "l"(p), "f"(v.x), "f"(v.y), "f"(v.z), "f"(v.w) : "memory");
    }
}

// ---------------- launch ----------------
extern "C" void kernel_launch(void* const* d_in, const int* in_sizes, int n_in,
                              void* d_out, int out_size) {
    const float* x       = (const float*)d_in[0];
    const float* weights = (const float*)d_in[1];
    const float* roots   = (const float*)d_in[2];
    const float* biases  = (const float*)d_in[3];
    const void*  ei      = d_in[4];
    const void*  et      = d_in[5];

    cudaFuncSetAttribute(gemm_kernel, cudaFuncAttributeMaxDynamicSharedMemorySize, SMEM_TOTAL);

    int sc_blocks = (EE * 32 + 255) / 256;

    detect_kernel<<<1, 1>>>((const int*)ei);
    conv_w_kernel<<<(3 * GG * DD * DD + 255) / 256, 256>>>(weights, roots);
    conv_x_kernel<<<(NN * DD + 255) / 256, 256>>>(x);

    dim3 ggrid((NN + BM - 1) / BM, CO / BN);   // 391 x 18
    for (int l = 0; l < 3; l++) {
        gemm_kernel<<<ggrid, 256, SMEM_TOTAL>>>(biases + (size_t)l * DD, l);
        scatter_kernel<<<sc_blocks, 256>>>(ei, et);
        if (l < 2)
            act_split_kernel<<<(NN * DD + 255) / 256, 256>>>();
        else
            act_final_kernel<<<(NN * DD / 4 + 255) / 256, 256>>>((float*)d_out);
    }
}

// round 6
// speedup vs baseline: 2.0433x; 1.1439x over previous
#include <cuda_runtime.h>
#include <cuda_bf16.h>
#include <cstdint>
#include <cstddef>

#define NN 50000
#define DD 256
#define RR 8
#define EE 300000
#define CO 2304
#define ROOTOFF 2048
#define GG 9            // 8 relations + root

// ---------------- device scratch ----------------
__device__ __align__(256) float g_Y[(size_t)NN * CO];                     // ~461 MB
__device__ __align__(256) __nv_bfloat16 g_Ahi[(size_t)NN * DD];
__device__ __align__(256) __nv_bfloat16 g_Alo[(size_t)NN * DD];
__device__ __align__(256) __nv_bfloat16 g_Whi[(size_t)3 * GG * DD * DD];  // [l][g][n][k]
__device__ __align__(256) __nv_bfloat16 g_Wlo[(size_t)3 * GG * DD * DD];
__device__ int g_idx64;

// ---------------- small kernels ----------------
__global__ void detect_kernel(const int* __restrict__ ei32) {
    int allzero = 1;
    for (int i = 1; i < 64; i += 2)
        if (ei32[i] != 0) allzero = 0;
    g_idx64 = allzero;
}

// Split-convert weights+roots, transposed to [l][g][n][k] (k contiguous).
__global__ void conv_w_kernel(const float* __restrict__ weights, const float* __restrict__ roots) {
    size_t i = (size_t)blockIdx.x * 256 + threadIdx.x;
    if (i >= (size_t)3 * GG * DD * DD) return;
    int k = (int)(i & 255);
    int n = (int)((i >> 8) & 255);
    int lg = (int)(i >> 16);
    int l = lg / GG, g = lg % GG;
    float w = (g < 8) ? weights[(((size_t)(l * 8 + g)) * DD + k) * DD + n]
                      : roots[((size_t)l * DD + k) * DD + n];
    __nv_bfloat16 hi = __float2bfloat16(w);
    __nv_bfloat16 lo = __float2bfloat16(w - __bfloat162float(hi));
    g_Whi[i] = hi;
    g_Wlo[i] = lo;
}

__global__ void conv_x_kernel(const float* __restrict__ x) {
    int i = blockIdx.x * 256 + threadIdx.x;
    if (i >= NN * DD) return;
    float a = x[i];
    __nv_bfloat16 hi = __float2bfloat16(a);
    g_Ahi[i] = hi;
    g_Alo[i] = __float2bfloat16(a - __bfloat162float(hi));
}

// relu(g_Y root section) -> split bf16 hi/lo for next layer's A
__global__ void act_split_kernel() {
    int i = blockIdx.x * 256 + threadIdx.x;
    if (i >= NN * DD) return;
    int n = i >> 8, j = i & 255;
    float v = fmaxf(g_Y[(size_t)n * CO + ROOTOFF + j], 0.f);
    __nv_bfloat16 hi = __float2bfloat16(v);
    g_Ahi[i] = hi;
    g_Alo[i] = __float2bfloat16(v - __bfloat162float(hi));
}

__global__ void act_final_kernel(float* __restrict__ out) {
    int idx = blockIdx.x * 256 + threadIdx.x;
    if (idx >= NN * (DD / 4)) return;
    int n = idx / (DD / 4);
    int j = idx % (DD / 4);
    float4 v = *(const float4*)(g_Y + (size_t)n * CO + ROOTOFF + j * 4);
    float4 r;
    r.x = 1.f / (1.f + expf(-v.x));
    r.y = 1.f / (1.f + expf(-v.y));
    r.z = 1.f / (1.f + expf(-v.z));
    r.w = 1.f / (1.f + expf(-v.w));
    *(float4*)(out + (size_t)idx * 4) = r;
}

// ---------------- HMMA (mma.sync) GEMM ----------------
// C[50000, 2304] = A @ Bcat via 3-term bf16 split, m16n8k16 bf16 MMA.
#define BM 128
#define BN 128
#define BK 32
#define STAGES 2
#define LDS_B 80                       // padded smem row stride in bytes (conflict-free)
#define ARR (128 * LDS_B)              // 10240 bytes per 128x32 bf16 array
#define OFF_AHI 0
#define OFF_ALO ARR
#define OFF_BHI (2 * ARR)
#define OFF_BLO (3 * ARR)
#define STAGE_BYTES (4 * ARR)          // 40960
#define SMEM_TOTAL (STAGES * STAGE_BYTES)  // 81920 -> 2 CTAs/SM

#define CP_ASYNC16(dst, src, srcsz) \
    asm volatile("cp.async.cg.shared.global [%0], [%1], 16, %2;" \
                 :: "r"(dst), "l"(src), "r"(srcsz) : "memory")
#define CP_COMMIT() asm volatile("cp.async.commit_group;" ::: "memory")
#define CP_WAIT1()  asm volatile("cp.async.wait_group 1;" ::: "memory")

__device__ __forceinline__ uint32_t smem_u32(const void* p) {
    uint32_t a;
    asm("{ .reg .u64 t; cvta.to.shared.u64 t, %1; cvt.u32.u64 %0, t; }" : "=r"(a) : "l"(p));
    return a;
}

__device__ __forceinline__ void mma16816(float* d, const uint32_t* a, const uint32_t* b) {
    asm volatile(
        "mma.sync.aligned.m16n8k16.row.col.f32.bf16.bf16.f32 "
        "{%0,%1,%2,%3}, {%4,%5,%6,%7}, {%8,%9}, {%0,%1,%2,%3};"
        : "+f"(d[0]), "+f"(d[1]), "+f"(d[2]), "+f"(d[3])
        : "r"(a[0]), "r"(a[1]), "r"(a[2]), "r"(a[3]), "r"(b[0]), "r"(b[1]));
}

__global__ __launch_bounds__(256, 2)
void gemm_kernel(const float* __restrict__ bias, int lay) {
    extern __shared__ char smem[];
    const uint32_t sb = smem_u32(smem);
    const int t = threadIdx.x;
    const int wid = t >> 5, lane = t & 31;
    const int g = lane >> 2, t4 = lane & 3;
    const int m0 = blockIdx.x * BM;
    const int nt = blockIdx.y;
    const int warp_m = wid & 3, warp_n = wid >> 2;   // 4 x 2 warp grid

    const int gidx = nt >> 1, nh = nt & 1;
    const __nv_bfloat16* Bh = g_Whi + ((size_t)(lay * GG + gidx) * DD + nh * 128) * DD;
    const __nv_bfloat16* Bl = g_Wlo + ((size_t)(lay * GG + gidx) * DD + nh * 128) * DD;

    float acc[2][8][4];
#pragma unroll
    for (int mi = 0; mi < 2; mi++)
#pragma unroll
        for (int nj = 0; nj < 8; nj++)
#pragma unroll
            for (int q = 0; q < 4; q++) acc[mi][nj][q] = 0.f;

    // Per-thread chunk assignment: 512 16B-chunks per 128x32 array, 2 per thread.
    auto load_stage = [&](int kt, int stage) {
        const int k0 = kt * BK;
        const uint32_t stb = sb + stage * STAGE_BYTES;
#pragma unroll
        for (int i = 0; i < 2; i++) {
            int c = t + i * 256;                 // 0..511
            int row = c >> 2;
            int col8 = (c & 3) * 8;              // bf16 col of 16B chunk
            uint32_t doff = (uint32_t)(row * LDS_B + col8 * 2);
            int gr = m0 + row;
            uint32_t asz = (gr < NN) ? 16u : 0u; // zero-fill OOB rows
            int grc = (gr < NN) ? gr : 0;
            CP_ASYNC16(stb + OFF_AHI + doff, g_Ahi + (size_t)grc * DD + k0 + col8, asz);
            CP_ASYNC16(stb + OFF_ALO + doff, g_Alo + (size_t)grc * DD + k0 + col8, asz);
            CP_ASYNC16(stb + OFF_BHI + doff, Bh + (size_t)row * DD + k0 + col8, 16u);
            CP_ASYNC16(stb + OFF_BLO + doff, Bl + (size_t)row * DD + k0 + col8, 16u);
        }
    };

#pragma unroll
    for (int s = 0; s < STAGES; s++) {
        load_stage(s, s);
        CP_COMMIT();
    }

    const int NKT = DD / BK;   // 8
    for (int kt = 0; kt < NKT; kt++) {
        CP_WAIT1();
        __syncthreads();
        const int stage = kt % STAGES;
        const char* stp = smem + stage * STAGE_BYTES;

#pragma unroll
        for (int h = 0; h < 2; h++) {            // two k16 halves of BK=32
            uint32_t ahi[2][4], alo[2][4], bhi[8][2], blo[8][2];
#pragma unroll
            for (int mi = 0; mi < 2; mi++) {
                int arow = warp_m * 32 + mi * 16 + g;
                const char* pa = stp + arow * LDS_B + (h * 16 + t4 * 2) * 2;
                ahi[mi][0] = *(const uint32_t*)(pa + OFF_AHI);
                ahi[mi][1] = *(const uint32_t*)(pa + OFF_AHI + 8 * LDS_B);
                ahi[mi][2] = *(const uint32_t*)(pa + OFF_AHI + 16);
                ahi[mi][3] = *(const uint32_t*)(pa + OFF_AHI + 8 * LDS_B + 16);
                alo[mi][0] = *(const uint32_t*)(pa + OFF_ALO);
                alo[mi][1] = *(const uint32_t*)(pa + OFF_ALO + 8 * LDS_B);
                alo[mi][2] = *(const uint32_t*)(pa + OFF_ALO + 16);
                alo[mi][3] = *(const uint32_t*)(pa + OFF_ALO + 8 * LDS_B + 16);
            }
#pragma unroll
            for (int nj = 0; nj < 8; nj++) {
                int brow = warp_n * 64 + nj * 8 + g;
                const char* pb = stp + brow * LDS_B + (h * 16 + t4 * 2) * 2;
                bhi[nj][0] = *(const uint32_t*)(pb + OFF_BHI);
                bhi[nj][1] = *(const uint32_t*)(pb + OFF_BHI + 16);
                blo[nj][0] = *(const uint32_t*)(pb + OFF_BLO);
                blo[nj][1] = *(const uint32_t*)(pb + OFF_BLO + 16);
            }
#pragma unroll
            for (int mi = 0; mi < 2; mi++)
#pragma unroll
                for (int nj = 0; nj < 8; nj++) {
                    mma16816(acc[mi][nj], ahi[mi], bhi[nj]);
                    mma16816(acc[mi][nj], ahi[mi], blo[nj]);
                    mma16816(acc[mi][nj], alo[mi], bhi[nj]);
                }
        }
        __syncthreads();
        if (kt + STAGES < NKT) load_stage(kt + STAGES, (kt + STAGES) % STAGES);
        CP_COMMIT();                              // keep group count uniform
    }

    // Epilogue: write C (+bias for root tiles) straight to g_Y.
    const bool isroot = (nt >= 16);
#pragma unroll
    for (int mi = 0; mi < 2; mi++) {
        int row0 = m0 + warp_m * 32 + mi * 16 + g;
#pragma unroll
        for (int nj = 0; nj < 8; nj++) {
            int col = nt * BN + warp_n * 64 + nj * 8 + t4 * 2;
            float b0 = 0.f, b1 = 0.f;
            if (isroot) {
                b0 = bias[col - ROOTOFF];
                b1 = bias[col + 1 - ROOTOFF];
            }
            if (row0 < NN) {
                float2 v = make_float2(acc[mi][nj][0] + b0, acc[mi][nj][1] + b1);
                *(float2*)(g_Y + (size_t)row0 * CO + col) = v;
            }
            if (row0 + 8 < NN) {
                float2 v = make_float2(acc[mi][nj][2] + b0, acc[mi][nj][3] + b1);
                *(float2*)(g_Y + (size_t)(row0 + 8) * CO + col) = v;
            }
        }
    }
}

// ---------------- scatter ----------------
__global__ void scatter_kernel(const void* __restrict__ ei, const void* __restrict__ et) {
    int w = (blockIdx.x * blockDim.x + threadIdx.x) >> 5;
    int lane = threadIdx.x & 31;
    if (w >= EE) return;
    long long src, dst, rel;
    if (g_idx64) {
        src = ((const long long*)ei)[w];
        dst = ((const long long*)ei)[EE + w];
        rel = ((const long long*)et)[w];
    } else {
        src = ((const int*)ei)[w];
        dst = ((const int*)ei)[EE + w];
        rel = ((const int*)et)[w];
    }
    if ((unsigned long long)src >= NN || (unsigned long long)dst >= NN ||
        (unsigned long long)rel >= RR) return;
    const float4* srow = (const float4*)(g_Y + (size_t)src * CO + rel * DD);
    float* drow = g_Y + (size_t)dst * CO + ROOTOFF;
#pragma unroll
    for (int i = 0; i < 2; i++) {
        float4 v = srow[lane + 32 * i];
        float* p = drow + (size_t)(lane + 32 * i) * 4;
        asm volatile("red.global.add.v4.f32 [%0], {%1, %2, %3, %4};"
                     :: "l"(p), "f"(v.x), "f"(v.y), "f"(v.z), "f"(v.w) : "memory");
    }
}

// ---------------- launch ----------------
extern "C" void kernel_launch(void* const* d_in, const int* in_sizes, int n_in,
                              void* d_out, int out_size) {
    const float* x       = (const float*)d_in[0];
    const float* weights = (const float*)d_in[1];
    const float* roots   = (const float*)d_in[2];
    const float* biases  = (const float*)d_in[3];
    const void*  ei      = d_in[4];
    const void*  et      = d_in[5];

    cudaFuncSetAttribute(gemm_kernel, cudaFuncAttributeMaxDynamicSharedMemorySize, SMEM_TOTAL);

    int sc_blocks = (EE * 32 + 255) / 256;

    detect_kernel<<<1, 1>>>((const int*)ei);
    conv_w_kernel<<<(3 * GG * DD * DD + 255) / 256, 256>>>(weights, roots);
    conv_x_kernel<<<(NN * DD + 255) / 256, 256>>>(x);

    dim3 ggrid((NN + BM - 1) / BM, CO / BN);   // 391 x 18
    for (int l = 0; l < 3; l++) {
        gemm_kernel<<<ggrid, 256, SMEM_TOTAL>>>(biases + (size_t)l * DD, l);
        scatter_kernel<<<sc_blocks, 256>>>(ei, et);
        if (l < 2)
            act_split_kernel<<<(NN * DD + 255) / 256, 256>>>();
        else
            act_final_kernel<<<(NN * DD / 4 + 255) / 256, 256>>>((float*)d_out);
    }
}

// round 7
// speedup vs baseline: 2.1575x; 1.0559x over previous
#include <cuda_runtime.h>
#include <cuda_bf16.h>
#include <cstdint>
#include <cstddef>

#define NN 50000
#define DD 256
#define RR 8
#define EE 300000
#define CO 2304
#define ROOTOFF 2048
#define GG 9            // 8 relations + root

// ---------------- device scratch ----------------
__device__ __align__(256) float g_Y[(size_t)NN * CO];                     // ~461 MB
__device__ __align__(256) __nv_bfloat16 g_Ahi[(size_t)NN * DD];
__device__ __align__(256) __nv_bfloat16 g_Alo[(size_t)NN * DD];
__device__ __align__(256) __nv_bfloat16 g_Whi[(size_t)3 * GG * DD * DD];  // [l][g][n][k]
__device__ __align__(256) __nv_bfloat16 g_Wlo[(size_t)3 * GG * DD * DD];
__device__ int g_idx64;

// ---------------- small kernels ----------------
__global__ void detect_kernel(const int* __restrict__ ei32) {
    int allzero = 1;
    for (int i = 1; i < 64; i += 2)
        if (ei32[i] != 0) allzero = 0;
    g_idx64 = allzero;
}

// Split-convert weights+roots, transposed to [l][g][n][k] (k contiguous).
__global__ void conv_w_kernel(const float* __restrict__ weights, const float* __restrict__ roots) {
    size_t i = (size_t)blockIdx.x * 256 + threadIdx.x;
    if (i >= (size_t)3 * GG * DD * DD) return;
    int k = (int)(i & 255);
    int n = (int)((i >> 8) & 255);
    int lg = (int)(i >> 16);
    int l = lg / GG, g = lg % GG;
    float w = (g < 8) ? weights[(((size_t)(l * 8 + g)) * DD + k) * DD + n]
                      : roots[((size_t)l * DD + k) * DD + n];
    __nv_bfloat16 hi = __float2bfloat16(w);
    __nv_bfloat16 lo = __float2bfloat16(w - __bfloat162float(hi));
    g_Whi[i] = hi;
    g_Wlo[i] = lo;
}

__global__ void conv_x_kernel(const float* __restrict__ x) {
    int i = blockIdx.x * 256 + threadIdx.x;
    if (i >= NN * DD) return;
    float a = x[i];
    __nv_bfloat16 hi = __float2bfloat16(a);
    g_Ahi[i] = hi;
    g_Alo[i] = __float2bfloat16(a - __bfloat162float(hi));
}

// relu(g_Y root section) -> split bf16 hi/lo for next layer's A
__global__ void act_split_kernel() {
    int i = blockIdx.x * 256 + threadIdx.x;
    if (i >= NN * DD) return;
    int n = i >> 8, j = i & 255;
    float v = fmaxf(g_Y[(size_t)n * CO + ROOTOFF + j], 0.f);
    __nv_bfloat16 hi = __float2bfloat16(v);
    g_Ahi[i] = hi;
    g_Alo[i] = __float2bfloat16(v - __bfloat162float(hi));
}

__global__ void act_final_kernel(float* __restrict__ out) {
    int idx = blockIdx.x * 256 + threadIdx.x;
    if (idx >= NN * (DD / 4)) return;
    int n = idx / (DD / 4);
    int j = idx % (DD / 4);
    float4 v = *(const float4*)(g_Y + (size_t)n * CO + ROOTOFF + j * 4);
    float4 r;
    r.x = 1.f / (1.f + expf(-v.x));
    r.y = 1.f / (1.f + expf(-v.y));
    r.z = 1.f / (1.f + expf(-v.z));
    r.w = 1.f / (1.f + expf(-v.w));
    *(float4*)(out + (size_t)idx * 4) = r;
}

// ---------------- HMMA (mma.sync) GEMM ----------------
// C[50000, 2304] = A @ Bcat via 3-term bf16 split, m16n8k16 bf16 MMA.
#define BM 128
#define BN 128
#define BK 32
#define STAGES 2
#define LDS_B 80                       // padded smem row stride in bytes (conflict-free)
#define ARR (128 * LDS_B)              // 10240 bytes per 128x32 bf16 array
#define OFF_AHI 0
#define OFF_ALO ARR
#define OFF_BHI (2 * ARR)
#define OFF_BLO (3 * ARR)
#define STAGE_BYTES (4 * ARR)          // 40960
#define SMEM_TOTAL (STAGES * STAGE_BYTES)  // 81920 -> 2 CTAs/SM

#define CP_ASYNC16(dst, src, srcsz) \
    asm volatile("cp.async.cg.shared.global [%0], [%1], 16, %2;" \
                 :: "r"(dst), "l"(src), "r"(srcsz) : "memory")
#define CP_COMMIT() asm volatile("cp.async.commit_group;" ::: "memory")
#define CP_WAIT1()  asm volatile("cp.async.wait_group 1;" ::: "memory")

// Non-trans ldmatrix x4: both A and B frags are plain row-major m8n8 here
// (B is pre-transposed to [n][k] so its mma fragment is k-contiguous too).
#define LDMX4(r, a) \
    asm volatile("ldmatrix.sync.aligned.m8n8.x4.shared.b16 {%0,%1,%2,%3}, [%4];" \
        : "=r"((r)[0]), "=r"((r)[1]), "=r"((r)[2]), "=r"((r)[3]) : "r"(a))

__device__ __forceinline__ uint32_t smem_u32(const void* p) {
    uint32_t a;
    asm("{ .reg .u64 t; cvta.to.shared.u64 t, %1; cvt.u32.u64 %0, t; }" : "=r"(a) : "l"(p));
    return a;
}

__device__ __forceinline__ void mma16816(float* d, const uint32_t* a, const uint32_t* b) {
    asm volatile(
        "mma.sync.aligned.m16n8k16.row.col.f32.bf16.bf16.f32 "
        "{%0,%1,%2,%3}, {%4,%5,%6,%7}, {%8,%9}, {%0,%1,%2,%3};"
        : "+f"(d[0]), "+f"(d[1]), "+f"(d[2]), "+f"(d[3])
        : "r"(a[0]), "r"(a[1]), "r"(a[2]), "r"(a[3]), "r"(b[0]), "r"(b[1]));
}

__global__ __launch_bounds__(256, 2)
void gemm_kernel(const float* __restrict__ bias, int lay) {
    extern __shared__ char smem[];
    const uint32_t sb = smem_u32(smem);
    const int t = threadIdx.x;
    const int wid = t >> 5, lane = t & 31;
    const int g = lane >> 2, t4 = lane & 3;
    const int m0 = blockIdx.x * BM;
    const int nt = blockIdx.y;
    const int warp_m = wid & 3, warp_n = wid >> 2;   // 4 x 2 warp grid

    const int gidx = nt >> 1, nh = nt & 1;
    const __nv_bfloat16* Bh = g_Whi + ((size_t)(lay * GG + gidx) * DD + nh * 128) * DD;
    const __nv_bfloat16* Bl = g_Wlo + ((size_t)(lay * GG + gidx) * DD + nh * 128) * DD;

    float acc[2][8][4];
#pragma unroll
    for (int mi = 0; mi < 2; mi++)
#pragma unroll
        for (int nj = 0; nj < 8; nj++)
#pragma unroll
            for (int q = 0; q < 4; q++) acc[mi][nj][q] = 0.f;

    // ldmatrix lane decomposition
    const int lr = lane & 7;                 // row within 8-row matrix
    const int l8 = (lane >> 3) & 1;          // matrix pair selector
    const int l16 = (lane >> 4) & 1;

    // Per-thread chunk assignment: 512 16B-chunks per 128x32 array, 2 per thread.
    auto load_stage = [&](int kt, int stage) {
        const int k0 = kt * BK;
        const uint32_t stb = sb + stage * STAGE_BYTES;
#pragma unroll
        for (int i = 0; i < 2; i++) {
            int c = t + i * 256;                 // 0..511
            int row = c >> 2;
            int col8 = (c & 3) * 8;              // bf16 col of 16B chunk
            uint32_t doff = (uint32_t)(row * LDS_B + col8 * 2);
            int gr = m0 + row;
            uint32_t asz = (gr < NN) ? 16u : 0u; // zero-fill OOB rows
            int grc = (gr < NN) ? gr : 0;
            CP_ASYNC16(stb + OFF_AHI + doff, g_Ahi + (size_t)grc * DD + k0 + col8, asz);
            CP_ASYNC16(stb + OFF_ALO + doff, g_Alo + (size_t)grc * DD + k0 + col8, asz);
            CP_ASYNC16(stb + OFF_BHI + doff, Bh + (size_t)row * DD + k0 + col8, 16u);
            CP_ASYNC16(stb + OFF_BLO + doff, Bl + (size_t)row * DD + k0 + col8, 16u);
        }
    };

#pragma unroll
    for (int s = 0; s < STAGES; s++) {
        load_stage(s, s);
        CP_COMMIT();
    }

    const int NKT = DD / BK;   // 8
    for (int kt = 0; kt < NKT; kt++) {
        CP_WAIT1();
        __syncthreads();
        const int stage = kt % STAGES;
        const uint32_t stf = sb + stage * STAGE_BYTES;

#pragma unroll
        for (int h = 0; h < 2; h++) {            // two k16 halves of BK=32
            uint32_t ahi[2][4], alo[2][4], bhi[4][4], blo[4][4];
            // A: lanes 0-7 rows+0 k+0 | 8-15 rows+8 k+0 | 16-23 rows+0 k+8 | 24-31 rows+8 k+8
            {
                uint32_t acol = (uint32_t)((h * 16 + l16 * 8) * 2);
#pragma unroll
                for (int mi = 0; mi < 2; mi++) {
                    uint32_t arow = (uint32_t)(warp_m * 32 + mi * 16 + l8 * 8 + lr);
                    uint32_t ao = stf + arow * LDS_B + acol;
                    LDMX4(ahi[mi], ao + OFF_AHI);
                    LDMX4(alo[mi], ao + OFF_ALO);
                }
            }
            // B: pair p covers nj=2p,2p+1. lanes 0-7 nj2p k+0 | 8-15 nj2p k+8
            //    | 16-23 nj2p+1 k+0 | 24-31 nj2p+1 k+8
            {
                uint32_t bcol = (uint32_t)((h * 16 + l8 * 8) * 2);
#pragma unroll
                for (int p = 0; p < 4; p++) {
                    uint32_t brow = (uint32_t)(warp_n * 64 + p * 16 + l16 * 8 + lr);
                    uint32_t bo = stf + brow * LDS_B + bcol;
                    LDMX4(bhi[p], bo + OFF_BHI);
                    LDMX4(blo[p], bo + OFF_BLO);
                }
            }
#pragma unroll
            for (int mi = 0; mi < 2; mi++)
#pragma unroll
                for (int p = 0; p < 4; p++) {
                    mma16816(acc[mi][2 * p],     ahi[mi], &bhi[p][0]);
                    mma16816(acc[mi][2 * p],     ahi[mi], &blo[p][0]);
                    mma16816(acc[mi][2 * p],     alo[mi], &bhi[p][0]);
                    mma16816(acc[mi][2 * p + 1], ahi[mi], &bhi[p][2]);
                    mma16816(acc[mi][2 * p + 1], ahi[mi], &blo[p][2]);
                    mma16816(acc[mi][2 * p + 1], alo[mi], &bhi[p][2]);
                }
        }
        __syncthreads();
        if (kt + STAGES < NKT) load_stage(kt + STAGES, (kt + STAGES) % STAGES);
        CP_COMMIT();                              // keep group count uniform
    }

    // Epilogue: write C (+bias for root tiles) straight to g_Y.
    const bool isroot = (nt >= 16);
#pragma unroll
    for (int mi = 0; mi < 2; mi++) {
        int row0 = m0 + warp_m * 32 + mi * 16 + g;
#pragma unroll
        for (int nj = 0; nj < 8; nj++) {
            int col = nt * BN + warp_n * 64 + nj * 8 + t4 * 2;
            float b0 = 0.f, b1 = 0.f;
            if (isroot) {
                b0 = bias[col - ROOTOFF];
                b1 = bias[col + 1 - ROOTOFF];
            }
            if (row0 < NN) {
                float2 v = make_float2(acc[mi][nj][0] + b0, acc[mi][nj][1] + b1);
                *(float2*)(g_Y + (size_t)row0 * CO + col) = v;
            }
            if (row0 + 8 < NN) {
                float2 v = make_float2(acc[mi][nj][2] + b0, acc[mi][nj][3] + b1);
                *(float2*)(g_Y + (size_t)(row0 + 8) * CO + col) = v;
            }
        }
    }
}

// ---------------- scatter ----------------
__global__ void scatter_kernel(const void* __restrict__ ei, const void* __restrict__ et) {
    int w = (blockIdx.x * blockDim.x + threadIdx.x) >> 5;
    int lane = threadIdx.x & 31;
    if (w >= EE) return;
    long long src, dst, rel;
    if (g_idx64) {
        src = ((const long long*)ei)[w];
        dst = ((const long long*)ei)[EE + w];
        rel = ((const long long*)et)[w];
    } else {
        src = ((const int*)ei)[w];
        dst = ((const int*)ei)[EE + w];
        rel = ((const int*)et)[w];
    }
    if ((unsigned long long)src >= NN || (unsigned long long)dst >= NN ||
        (unsigned long long)rel >= RR) return;
    const float4* srow = (const float4*)(g_Y + (size_t)src * CO + rel * DD);
    float* drow = g_Y + (size_t)dst * CO + ROOTOFF;
#pragma unroll
    for (int i = 0; i < 2; i++) {
        float4 v = srow[lane + 32 * i];
        float* p = drow + (size_t)(lane + 32 * i) * 4;
        asm volatile("red.global.add.v4.f32 [%0], {%1, %2, %3, %4};"
                     :: "l"(p), "f"(v.x), "f"(v.y), "f"(v.z), "f"(v.w) : "memory");
    }
}

// ---------------- launch ----------------
extern "C" void kernel_launch(void* const* d_in, const int* in_sizes, int n_in,
                              void* d_out, int out_size) {
    const float* x       = (const float*)d_in[0];
    const float* weights = (const float*)d_in[1];
    const float* roots   = (const float*)d_in[2];
    const float* biases  = (const float*)d_in[3];
    const void*  ei      = d_in[4];
    const void*  et      = d_in[5];

    cudaFuncSetAttribute(gemm_kernel, cudaFuncAttributeMaxDynamicSharedMemorySize, SMEM_TOTAL);

    int sc_blocks = (EE * 32 + 255) / 256;

    detect_kernel<<<1, 1>>>((const int*)ei);
    conv_w_kernel<<<(3 * GG * DD * DD + 255) / 256, 256>>>(weights, roots);
    conv_x_kernel<<<(NN * DD + 255) / 256, 256>>>(x);

    dim3 ggrid((NN + BM - 1) / BM, CO / BN);   // 391 x 18
    for (int l = 0; l < 3; l++) {
        gemm_kernel<<<ggrid, 256, SMEM_TOTAL>>>(biases + (size_t)l * DD, l);
        scatter_kernel<<<sc_blocks, 256>>>(ei, et);
        if (l < 2)
            act_split_kernel<<<(NN * DD + 255) / 256, 256>>>();
        else
            act_final_kernel<<<(NN * DD / 4 + 255) / 256, 256>>>((float*)d_out);
    }
}

// round 9
// speedup vs baseline: 2.4575x; 1.1390x over previous
#include <cuda_runtime.h>
#include <cuda_bf16.h>
#include <cstdint>
#include <cstddef>

#define NN 50000
#define DD 256
#define RR 8
#define EE 300000
#define CO 2304
#define ROOTOFF 2048
#define GG 9            // 8 relations + root

// ---------------- device scratch ----------------
__device__ __align__(256) float g_Y[(size_t)NN * CO];                     // ~461 MB
__device__ __align__(256) __nv_bfloat16 g_Ahi[(size_t)NN * DD];
__device__ __align__(256) __nv_bfloat16 g_Alo[(size_t)NN * DD];
__device__ __align__(256) __nv_bfloat16 g_Whi[(size_t)3 * GG * DD * DD];  // [l][g][n][k]
__device__ __align__(256) __nv_bfloat16 g_Wlo[(size_t)3 * GG * DD * DD];
__device__ int g_idx64;

// ---------------- small kernels ----------------
__global__ void detect_kernel(const int* __restrict__ ei32) {
    int allzero = 1;
    for (int i = 1; i < 64; i += 2)
        if (ei32[i] != 0) allzero = 0;
    g_idx64 = allzero;
}

// Split-convert weights+roots, transposed to [l][g][n][k] (k contiguous).
__global__ void conv_w_kernel(const float* __restrict__ weights, const float* __restrict__ roots) {
    size_t i = (size_t)blockIdx.x * 256 + threadIdx.x;
    if (i >= (size_t)3 * GG * DD * DD) return;
    int k = (int)(i & 255);
    int n = (int)((i >> 8) & 255);
    int lg = (int)(i >> 16);
    int l = lg / GG, g = lg % GG;
    float w = (g < 8) ? weights[(((size_t)(l * 8 + g)) * DD + k) * DD + n]
                      : roots[((size_t)l * DD + k) * DD + n];
    __nv_bfloat16 hi = __float2bfloat16(w);
    __nv_bfloat16 lo = __float2bfloat16(w - __bfloat162float(hi));
    g_Whi[i] = hi;
    g_Wlo[i] = lo;
}

__global__ void conv_x_kernel(const float* __restrict__ x) {
    int i = blockIdx.x * 256 + threadIdx.x;
    if (i >= NN * DD) return;
    float a = x[i];
    __nv_bfloat16 hi = __float2bfloat16(a);
    g_Ahi[i] = hi;
    g_Alo[i] = __float2bfloat16(a - __bfloat162float(hi));
}

// relu(g_Y root section) -> split bf16 hi/lo for next layer's A
__global__ void act_split_kernel() {
    int i = blockIdx.x * 256 + threadIdx.x;
    if (i >= NN * DD) return;
    int n = i >> 8, j = i & 255;
    float v = fmaxf(g_Y[(size_t)n * CO + ROOTOFF + j], 0.f);
    __nv_bfloat16 hi = __float2bfloat16(v);
    g_Ahi[i] = hi;
    g_Alo[i] = __float2bfloat16(v - __bfloat162float(hi));
}

__global__ void act_final_kernel(float* __restrict__ out) {
    int idx = blockIdx.x * 256 + threadIdx.x;
    if (idx >= NN * (DD / 4)) return;
    int n = idx / (DD / 4);
    int j = idx % (DD / 4);
    float4 v = *(const float4*)(g_Y + (size_t)n * CO + ROOTOFF + j * 4);
    float4 r;
    r.x = 1.f / (1.f + expf(-v.x));
    r.y = 1.f / (1.f + expf(-v.y));
    r.z = 1.f / (1.f + expf(-v.z));
    r.w = 1.f / (1.f + expf(-v.w));
    *(float4*)(out + (size_t)idx * 4) = r;
}

// ---------------- HMMA (mma.sync) GEMM ----------------
// C[50000, 2304] = A @ Bcat via 3-term bf16 split, m16n8k16 bf16 MMA.
// SMEM: 64B rows (no pad) + XOR chunk swizzle phys = j ^ ((row>>1)&3).
// All addresses 16B-aligned; ldmatrix/cp.async conflict-free (8 rows cover
// 8 distinct 16B chunks mod 128B).
#define BM 128
#define BN 128
#define BK 32
#define STAGES 3
#define LDS_B 64
#define ARR (128 * LDS_B)              // 8192 bytes per 128x32 bf16 array
#define OFF_AHI 0
#define OFF_ALO ARR
#define OFF_BHI (2 * ARR)
#define OFF_BLO (3 * ARR)
#define STAGE_BYTES (4 * ARR)          // 32768
#define SMEM_TOTAL (STAGES * STAGE_BYTES)  // 98304 -> 2 CTAs/SM

#define CP_ASYNC16(dst, src, srcsz) \
    asm volatile("cp.async.cg.shared.global [%0], [%1], 16, %2;" \
                 :: "r"(dst), "l"(src), "r"(srcsz) : "memory")
#define CP_COMMIT() asm volatile("cp.async.commit_group;" ::: "memory")
#define CP_WAIT1()  asm volatile("cp.async.wait_group 1;" ::: "memory")

// Non-trans ldmatrix x4: both A and B frags are plain row-major m8n8 here
// (B is pre-transposed to [n][k] so its mma fragment is k-contiguous too).
#define LDMX4(r, a) \
    asm volatile("ldmatrix.sync.aligned.m8n8.x4.shared.b16 {%0,%1,%2,%3}, [%4];" \
        : "=r"((r)[0]), "=r"((r)[1]), "=r"((r)[2]), "=r"((r)[3]) : "r"(a))

__device__ __forceinline__ uint32_t smem_u32(const void* p) {
    uint32_t a;
    asm("{ .reg .u64 t; cvta.to.shared.u64 t, %1; cvt.u32.u64 %0, t; }" : "=r"(a) : "l"(p));
    return a;
}

// swizzled byte offset of 16B chunk j in row r
__device__ __forceinline__ uint32_t swz(uint32_t row, uint32_t j) {
    return row * LDS_B + ((j ^ ((row >> 1) & 3u)) << 4);
}

__device__ __forceinline__ void mma16816(float* d, const uint32_t* a, const uint32_t* b) {
    asm volatile(
        "mma.sync.aligned.m16n8k16.row.col.f32.bf16.bf16.f32 "
        "{%0,%1,%2,%3}, {%4,%5,%6,%7}, {%8,%9}, {%0,%1,%2,%3};"
        : "+f"(d[0]), "+f"(d[1]), "+f"(d[2]), "+f"(d[3])
        : "r"(a[0]), "r"(a[1]), "r"(a[2]), "r"(a[3]), "r"(b[0]), "r"(b[1]));
}

__global__ __launch_bounds__(256, 2)
void gemm_kernel(const float* __restrict__ bias, int lay) {
    extern __shared__ char smem[];
    const uint32_t sb = smem_u32(smem);
    const int t = threadIdx.x;
    const int wid = t >> 5, lane = t & 31;
    const int g = lane >> 2, t4 = lane & 3;
    const int m0 = blockIdx.x * BM;
    const int nt = blockIdx.y;
    const int warp_m = wid & 3, warp_n = wid >> 2;   // 4 x 2 warp grid

    const int gidx = nt >> 1, nh = nt & 1;
    const __nv_bfloat16* Bh = g_Whi + ((size_t)(lay * GG + gidx) * DD + nh * 128) * DD;
    const __nv_bfloat16* Bl = g_Wlo + ((size_t)(lay * GG + gidx) * DD + nh * 128) * DD;

    float acc[2][8][4];
#pragma unroll
    for (int mi = 0; mi < 2; mi++)
#pragma unroll
        for (int nj = 0; nj < 8; nj++)
#pragma unroll
            for (int q = 0; q < 4; q++) acc[mi][nj][q] = 0.f;

    // ldmatrix lane decomposition
    const int lr = lane & 7;                 // row within 8-row matrix
    const int l8 = (lane >> 3) & 1;          // matrix pair selector
    const int l16 = (lane >> 4) & 1;

    // Per-thread chunk assignment: 512 16B-chunks per 128x32 array, 2 per thread.
    auto load_stage = [&](int kt, int stage) {
        const int k0 = kt * BK;
        const uint32_t stb = sb + stage * STAGE_BYTES;
#pragma unroll
        for (int i = 0; i < 2; i++) {
            int c = t + i * 256;                 // 0..511
            uint32_t row = (uint32_t)(c >> 2);
            uint32_t j = (uint32_t)(c & 3);      // logical 16B chunk (8 bf16)
            uint32_t doff = swz(row, j);
            int col8 = (int)j * 8;
            int gr = m0 + (int)row;
            uint32_t asz = (gr < NN) ? 16u : 0u; // zero-fill OOB rows
            int grc = (gr < NN) ? gr : 0;
            CP_ASYNC16(stb + OFF_AHI + doff, g_Ahi + (size_t)grc * DD + k0 + col8, asz);
            CP_ASYNC16(stb + OFF_ALO + doff, g_Alo + (size_t)grc * DD + k0 + col8, asz);
            CP_ASYNC16(stb + OFF_BHI + doff, Bh + (size_t)row * DD + k0 + col8, 16u);
            CP_ASYNC16(stb + OFF_BLO + doff, Bl + (size_t)row * DD + k0 + col8, 16u);
        }
    };

    // Prologue: 2 stages in flight.
    load_stage(0, 0);
    CP_COMMIT();
    load_stage(1, 1);
    CP_COMMIT();

    const int NKT = DD / BK;   // 8
    for (int kt = 0; kt < NKT; kt++) {
        CP_WAIT1();            // stage kt landed
        __syncthreads();       // also protects buffer (kt+2)%3 (computed at kt-1)

        // Prefetch stage kt+2 BEFORE compute (hides load latency under MMAs).
        if (kt + 2 < NKT) load_stage(kt + 2, (kt + 2) % STAGES);
        CP_COMMIT();           // unconditional: keeps group accounting uniform

        const uint32_t stf = sb + (kt % STAGES) * STAGE_BYTES;

#pragma unroll
        for (int h = 0; h < 2; h++) {            // two k16 halves of BK=32
            uint32_t ahi[2][4], alo[2][4], bhi[4][4], blo[4][4];
            // A: lanes 0-7 rows+0 k+0 | 8-15 rows+8 k+0 | 16-23 rows+0 k+8 | 24-31 rows+8 k+8
            {
                uint32_t jA = (uint32_t)(h * 2 + l16);   // logical 16B chunk
#pragma unroll
                for (int mi = 0; mi < 2; mi++) {
                    uint32_t arow = (uint32_t)(warp_m * 32 + mi * 16 + l8 * 8 + lr);
                    uint32_t ao = stf + swz(arow, jA);
                    LDMX4(ahi[mi], ao + OFF_AHI);
                    LDMX4(alo[mi], ao + OFF_ALO);
                }
            }
            // B: pair p covers nj=2p,2p+1. lanes 0-7 nj2p k+0 | 8-15 nj2p k+8
            //    | 16-23 nj2p+1 k+0 | 24-31 nj2p+1 k+8
            {
                uint32_t jB = (uint32_t)(h * 2 + l8);
#pragma unroll
                for (int p = 0; p < 4; p++) {
                    uint32_t brow = (uint32_t)(warp_n * 64 + p * 16 + l16 * 8 + lr);
                    uint32_t bo = stf + swz(brow, jB);
                    LDMX4(bhi[p], bo + OFF_BHI);
                    LDMX4(blo[p], bo + OFF_BLO);
                }
            }
            // Term-major order: RAW distance on each acc group = 16 MMAs.
#pragma unroll
            for (int term = 0; term < 3; term++) {
#pragma unroll
                for (int mi = 0; mi < 2; mi++)
#pragma unroll
                    for (int p = 0; p < 4; p++) {
                        const uint32_t* af = (term == 2) ? alo[mi] : ahi[mi];
                        const uint32_t* bf = (term == 1) ? blo[p] : bhi[p];
                        mma16816(acc[mi][2 * p],     af, &bf[0]);
                        mma16816(acc[mi][2 * p + 1], af, &bf[2]);
                    }
            }
        }
    }

    // Epilogue: write C (+bias for root tiles) straight to g_Y.
    const bool isroot = (nt >= 16);
#pragma unroll
    for (int mi = 0; mi < 2; mi++) {
        int row0 = m0 + warp_m * 32 + mi * 16 + g;
#pragma unroll
        for (int nj = 0; nj < 8; nj++) {
            int col = nt * BN + warp_n * 64 + nj * 8 + t4 * 2;
            float b0 = 0.f, b1 = 0.f;
            if (isroot) {
                b0 = bias[col - ROOTOFF];
                b1 = bias[col + 1 - ROOTOFF];
            }
            if (row0 < NN) {
                float2 v = make_float2(acc[mi][nj][0] + b0, acc[mi][nj][1] + b1);
                *(float2*)(g_Y + (size_t)row0 * CO + col) = v;
            }
            if (row0 + 8 < NN) {
                float2 v = make_float2(acc[mi][nj][2] + b0, acc[mi][nj][3] + b1);
                *(float2*)(g_Y + (size_t)(row0 + 8) * CO + col) = v;
            }
        }
    }
}

// ---------------- scatter ----------------
__global__ void scatter_kernel(const void* __restrict__ ei, const void* __restrict__ et) {
    int w = (blockIdx.x * blockDim.x + threadIdx.x) >> 5;
    int lane = threadIdx.x & 31;
    if (w >= EE) return;
    long long src, dst, rel;
    if (g_idx64) {
        src = ((const long long*)ei)[w];
        dst = ((const long long*)ei)[EE + w];
        rel = ((const long long*)et)[w];
    } else {
        src = ((const int*)ei)[w];
        dst = ((const int*)ei)[EE + w];
        rel = ((const int*)et)[w];
    }
    if ((unsigned long long)src >= NN || (unsigned long long)dst >= NN ||
        (unsigned long long)rel >= RR) return;
    const float4* srow = (const float4*)(g_Y + (size_t)src * CO + rel * DD);
    float* drow = g_Y + (size_t)dst * CO + ROOTOFF;
#pragma unroll
    for (int i = 0; i < 2; i++) {
        float4 v = srow[lane + 32 * i];
        float* p = drow + (size_t)(lane + 32 * i) * 4;
        asm volatile("red.global.add.v4.f32 [%0], {%1, %2, %3, %4};"
                     :: "l"(p), "f"(v.x), "f"(v.y), "f"(v.z), "f"(v.w) : "memory");
    }
}

// ---------------- launch ----------------
extern "C" void kernel_launch(void* const* d_in, const int* in_sizes, int n_in,
                              void* d_out, int out_size) {
    const float* x       = (const float*)d_in[0];
    const float* weights = (const float*)d_in[1];
    const float* roots   = (const float*)d_in[2];
    const float* biases  = (const float*)d_in[3];
    const void*  ei      = d_in[4];
    const void*  et      = d_in[5];

    cudaFuncSetAttribute(gemm_kernel, cudaFuncAttributeMaxDynamicSharedMemorySize, SMEM_TOTAL);

    int sc_blocks = (EE * 32 + 255) / 256;

    detect_kernel<<<1, 1>>>((const int*)ei);
    conv_w_kernel<<<(3 * GG * DD * DD + 255) / 256, 256>>>(weights, roots);
    conv_x_kernel<<<(NN * DD + 255) / 256, 256>>>(x);

    dim3 ggrid((NN + BM - 1) / BM, CO / BN);   // 391 x 18
    for (int l = 0; l < 3; l++) {
        gemm_kernel<<<ggrid, 256, SMEM_TOTAL>>>(biases + (size_t)l * DD, l);
        scatter_kernel<<<sc_blocks, 256>>>(ei, et);
        if (l < 2)
            act_split_kernel<<<(NN * DD + 255) / 256, 256>>>();
        else
            act_final_kernel<<<(NN * DD / 4 + 255) / 256, 256>>>((float*)d_out);
    }
}

// round 10
// speedup vs baseline: 2.7064x; 1.1013x over previous
#include <cuda_runtime.h>
#include <cuda_bf16.h>
#include <cstdint>
#include <cstddef>

#define NN 50000
#define DD 256
#define RR 8
#define EE 300000
#define GG 9            // 8 relations + root
#define NB (391 * 8)    // edge buckets: (src block) x relation

// ---------------- device scratch ----------------
__device__ __align__(256) float g_Yroot[(size_t)NN * DD];                 // 51.2 MB accumulator
__device__ __align__(256) __nv_bfloat16 g_Ahi[(size_t)NN * DD];
__device__ __align__(256) __nv_bfloat16 g_Alo[(size_t)NN * DD];
__device__ __align__(256) __nv_bfloat16 g_Whi[(size_t)3 * GG * DD * DD];  // [l][g][n][k]
__device__ __align__(256) __nv_bfloat16 g_Wlo[(size_t)3 * GG * DD * DD];
__device__ int g_idx64;
__device__ int g_cnt[NB];
__device__ int g_ofs[NB + 1];
__device__ int g_fill[NB];
__device__ uint32_t g_elist[EE];

// ---------------- edge helpers ----------------
__device__ __forceinline__ bool load_edge(const void* ei, const void* et, int w,
                                          int& src, int& dst, int& rel) {
    long long s, d, r;
    if (g_idx64) {
        s = ((const long long*)ei)[w];
        d = ((const long long*)ei)[EE + w];
        r = ((const long long*)et)[w];
    } else {
        s = ((const int*)ei)[w];
        d = ((const int*)ei)[EE + w];
        r = ((const int*)et)[w];
    }
    if ((unsigned long long)s >= NN || (unsigned long long)d >= NN ||
        (unsigned long long)r >= RR) return false;
    src = (int)s; dst = (int)d; rel = (int)r;
    return true;
}

__global__ void detect_kernel(const int* __restrict__ ei32) {
    int allzero = 1;
    for (int i = 1; i < 64; i += 2)
        if (ei32[i] != 0) allzero = 0;
    g_idx64 = allzero;
}

__global__ void zero_cnt_kernel() {
    int i = blockIdx.x * 256 + threadIdx.x;
    if (i < NB) g_cnt[i] = 0;
}

__global__ void count_kernel(const void* __restrict__ ei, const void* __restrict__ et) {
    int w = blockIdx.x * 256 + threadIdx.x;
    if (w >= EE) return;
    int src, dst, rel;
    if (!load_edge(ei, et, w, src, dst, rel)) return;
    atomicAdd(&g_cnt[(src >> 7) * RR + rel], 1);
}

// single-block exclusive scan of g_cnt -> g_ofs / g_fill (1024 thr x 4 buckets)
__global__ void scan_kernel() {
    __shared__ int s[1024];
    int t = threadIdx.x;
    int v[4], sum = 0;
#pragma unroll
    for (int i = 0; i < 4; i++) {
        int b = t * 4 + i;
        v[i] = (b < NB) ? g_cnt[b] : 0;
        sum += v[i];
    }
    s[t] = sum;
    __syncthreads();
    for (int off = 1; off < 1024; off <<= 1) {
        int x = (t >= off) ? s[t - off] : 0;
        __syncthreads();
        s[t] += x;
        __syncthreads();
    }
    int excl = s[t] - sum;
#pragma unroll
    for (int i = 0; i < 4; i++) {
        int b = t * 4 + i;
        if (b < NB) { g_ofs[b] = excl; g_fill[b] = excl; }
        excl += v[i];
    }
    if (t == 1023) g_ofs[NB] = excl;
}

__global__ void fill_kernel(const void* __restrict__ ei, const void* __restrict__ et) {
    int w = blockIdx.x * 256 + threadIdx.x;
    if (w >= EE) return;
    int src, dst, rel;
    if (!load_edge(ei, et, w, src, dst, rel)) return;
    int b = (src >> 7) * RR + rel;
    int pos = atomicAdd(&g_fill[b], 1);
    g_elist[pos] = ((uint32_t)(src & 127) << 17) | (uint32_t)dst;
}

// ---------------- conversion / activation ----------------
__global__ void conv_w_kernel(const float* __restrict__ weights, const float* __restrict__ roots) {
    size_t i = (size_t)blockIdx.x * 256 + threadIdx.x;
    if (i >= (size_t)3 * GG * DD * DD) return;
    int k = (int)(i & 255);
    int n = (int)((i >> 8) & 255);
    int lg = (int)(i >> 16);
    int l = lg / GG, g = lg % GG;
    float w = (g < 8) ? weights[(((size_t)(l * 8 + g)) * DD + k) * DD + n]
                      : roots[((size_t)l * DD + k) * DD + n];
    __nv_bfloat16 hi = __float2bfloat16(w);
    g_Whi[i] = hi;
    g_Wlo[i] = __float2bfloat16(w - __bfloat162float(hi));
}

__global__ void conv_x_kernel(const float* __restrict__ x) {
    int i = blockIdx.x * 256 + threadIdx.x;
    if (i >= NN * DD) return;
    float a = x[i];
    __nv_bfloat16 hi = __float2bfloat16(a);
    g_Ahi[i] = hi;
    g_Alo[i] = __float2bfloat16(a - __bfloat162float(hi));
}

__global__ void act_split_kernel() {
    int i = blockIdx.x * 256 + threadIdx.x;
    if (i >= NN * DD) return;
    float v = fmaxf(g_Yroot[i], 0.f);
    __nv_bfloat16 hi = __float2bfloat16(v);
    g_Ahi[i] = hi;
    g_Alo[i] = __float2bfloat16(v - __bfloat162float(hi));
}

__global__ void act_final_kernel(float* __restrict__ out) {
    int idx = blockIdx.x * 256 + threadIdx.x;
    if (idx >= NN * (DD / 4)) return;
    float4 v = *(const float4*)(g_Yroot + (size_t)idx * 4);
    float4 r;
    r.x = 1.f / (1.f + expf(-v.x));
    r.y = 1.f / (1.f + expf(-v.y));
    r.z = 1.f / (1.f + expf(-v.z));
    r.w = 1.f / (1.f + expf(-v.w));
    *(float4*)(out + (size_t)idx * 4) = r;
}

// ---------------- HMMA GEMM + fused scatter epilogue ----------------
#define BM 128
#define BN 128
#define BK 32
#define STAGES 3
#define LDS_B 64
#define ARR (128 * LDS_B)
#define OFF_AHI 0
#define OFF_ALO ARR
#define OFF_BHI (2 * ARR)
#define OFF_BLO (3 * ARR)
#define STAGE_BYTES (4 * ARR)              // 32768
#define SMEM_TOTAL (STAGES * STAGE_BYTES)  // 98304 -> 2 CTAs/SM
#define CS_STRIDE 132                      // fp32 C staging row stride (padded)

#define CP_ASYNC16(dst, src, srcsz) \
    asm volatile("cp.async.cg.shared.global [%0], [%1], 16, %2;" \
                 :: "r"(dst), "l"(src), "r"(srcsz) : "memory")
#define CP_COMMIT() asm volatile("cp.async.commit_group;" ::: "memory")
#define CP_WAIT1()  asm volatile("cp.async.wait_group 1;" ::: "memory")

#define LDMX4(r, a) \
    asm volatile("ldmatrix.sync.aligned.m8n8.x4.shared.b16 {%0,%1,%2,%3}, [%4];" \
        : "=r"((r)[0]), "=r"((r)[1]), "=r"((r)[2]), "=r"((r)[3]) : "r"(a))

__device__ __forceinline__ uint32_t smem_u32(const void* p) {
    uint32_t a;
    asm("{ .reg .u64 t; cvta.to.shared.u64 t, %1; cvt.u32.u64 %0, t; }" : "=r"(a) : "l"(p));
    return a;
}
__device__ __forceinline__ uint32_t swz(uint32_t row, uint32_t j) {
    return row * LDS_B + ((j ^ ((row >> 1) & 3u)) << 4);
}
__device__ __forceinline__ void mma16816(float* d, const uint32_t* a, const uint32_t* b) {
    asm volatile(
        "mma.sync.aligned.m16n8k16.row.col.f32.bf16.bf16.f32 "
        "{%0,%1,%2,%3}, {%4,%5,%6,%7}, {%8,%9}, {%0,%1,%2,%3};"
        : "+f"(d[0]), "+f"(d[1]), "+f"(d[2]), "+f"(d[3])
        : "r"(a[0]), "r"(a[1]), "r"(a[2]), "r"(a[3]), "r"(b[0]), "r"(b[1]));
}

// ntofs=16: root tiles (plain store + bias -> g_Yroot, initializes accumulator)
// ntofs=0 : relation tiles (stage C to smem, atomic-add bucket edges into g_Yroot)
__global__ __launch_bounds__(256, 2)
void gemm_kernel(const float* __restrict__ bias, int lay, int ntofs) {
    extern __shared__ char smem[];
    const uint32_t sb = smem_u32(smem);
    const int t = threadIdx.x;
    const int wid = t >> 5, lane = t & 31;
    const int g = lane >> 2, t4 = lane & 3;
    const int m0 = blockIdx.x * BM;
    const int nt = ntofs + blockIdx.y;
    const int warp_m = wid & 3, warp_n = wid >> 2;   // 4 x 2 warp grid

    const int group = nt >> 1, nh = nt & 1;          // group 0..7 rel, 8 root
    const __nv_bfloat16* Bh = g_Whi + ((size_t)(lay * GG + group) * DD + nh * 128) * DD;
    const __nv_bfloat16* Bl = g_Wlo + ((size_t)(lay * GG + group) * DD + nh * 128) * DD;

    float acc[2][8][4];
#pragma unroll
    for (int mi = 0; mi < 2; mi++)
#pragma unroll
        for (int nj = 0; nj < 8; nj++)
#pragma unroll
            for (int q = 0; q < 4; q++) acc[mi][nj][q] = 0.f;

    const int lr = lane & 7;
    const int l8 = (lane >> 3) & 1;
    const int l16 = (lane >> 4) & 1;

    auto load_stage = [&](int kt, int stage) {
        const int k0 = kt * BK;
        const uint32_t stb = sb + stage * STAGE_BYTES;
#pragma unroll
        for (int i = 0; i < 2; i++) {
            int c = t + i * 256;
            uint32_t row = (uint32_t)(c >> 2);
            uint32_t j = (uint32_t)(c & 3);
            uint32_t doff = swz(row, j);
            int col8 = (int)j * 8;
            int gr = m0 + (int)row;
            uint32_t asz = (gr < NN) ? 16u : 0u;
            int grc = (gr < NN) ? gr : 0;
            CP_ASYNC16(stb + OFF_AHI + doff, g_Ahi + (size_t)grc * DD + k0 + col8, asz);
            CP_ASYNC16(stb + OFF_ALO + doff, g_Alo + (size_t)grc * DD + k0 + col8, asz);
            CP_ASYNC16(stb + OFF_BHI + doff, Bh + (size_t)row * DD + k0 + col8, 16u);
            CP_ASYNC16(stb + OFF_BLO + doff, Bl + (size_t)row * DD + k0 + col8, 16u);
        }
    };

    load_stage(0, 0);
    CP_COMMIT();
    load_stage(1, 1);
    CP_COMMIT();

    const int NKT = DD / BK;   // 8
    for (int kt = 0; kt < NKT; kt++) {
        CP_WAIT1();
        __syncthreads();
        if (kt + 2 < NKT) load_stage(kt + 2, (kt + 2) % STAGES);
        CP_COMMIT();

        const uint32_t stf = sb + (kt % STAGES) * STAGE_BYTES;
#pragma unroll
        for (int h = 0; h < 2; h++) {
            uint32_t ahi[2][4], alo[2][4], bhi[4][4], blo[4][4];
            {
                uint32_t jA = (uint32_t)(h * 2 + l16);
#pragma unroll
                for (int mi = 0; mi < 2; mi++) {
                    uint32_t arow = (uint32_t)(warp_m * 32 + mi * 16 + l8 * 8 + lr);
                    uint32_t ao = stf + swz(arow, jA);
                    LDMX4(ahi[mi], ao + OFF_AHI);
                    LDMX4(alo[mi], ao + OFF_ALO);
                }
            }
            {
                uint32_t jB = (uint32_t)(h * 2 + l8);
#pragma unroll
                for (int p = 0; p < 4; p++) {
                    uint32_t brow = (uint32_t)(warp_n * 64 + p * 16 + l16 * 8 + lr);
                    uint32_t bo = stf + swz(brow, jB);
                    LDMX4(bhi[p], bo + OFF_BHI);
                    LDMX4(blo[p], bo + OFF_BLO);
                }
            }
#pragma unroll
            for (int term = 0; term < 3; term++) {
#pragma unroll
                for (int mi = 0; mi < 2; mi++)
#pragma unroll
                    for (int p = 0; p < 4; p++) {
                        const uint32_t* af = (term == 2) ? alo[mi] : ahi[mi];
                        const uint32_t* bf = (term == 1) ? blo[p] : bhi[p];
                        mma16816(acc[mi][2 * p],     af, &bf[0]);
                        mma16816(acc[mi][2 * p + 1], af, &bf[2]);
                    }
            }
        }
    }

    if (group == 8) {
        // Root epilogue: plain store + bias -> g_Yroot (initializes accumulator).
#pragma unroll
        for (int mi = 0; mi < 2; mi++) {
            int row0 = m0 + warp_m * 32 + mi * 16 + g;
#pragma unroll
            for (int nj = 0; nj < 8; nj++) {
                int c = nh * 128 + warp_n * 64 + nj * 8 + t4 * 2;
                float b0 = bias[c], b1 = bias[c + 1];
                if (row0 < NN)
                    *(float2*)(g_Yroot + (size_t)row0 * DD + c) =
                        make_float2(acc[mi][nj][0] + b0, acc[mi][nj][1] + b1);
                if (row0 + 8 < NN)
                    *(float2*)(g_Yroot + (size_t)(row0 + 8) * DD + c) =
                        make_float2(acc[mi][nj][2] + b0, acc[mi][nj][3] + b1);
            }
        }
    } else {
        // Fused scatter epilogue: stage C in smem, walk this (block, rel) bucket.
        __syncthreads();                       // all stage-buffer reads done
        float* cs = (float*)smem;              // [128][CS_STRIDE]
#pragma unroll
        for (int mi = 0; mi < 2; mi++) {
            int r0 = warp_m * 32 + mi * 16 + g;
#pragma unroll
            for (int nj = 0; nj < 8; nj++) {
                int cl = warp_n * 64 + nj * 8 + t4 * 2;
                *(float2*)(cs + r0 * CS_STRIDE + cl) =
                    make_float2(acc[mi][nj][0], acc[mi][nj][1]);
                *(float2*)(cs + (r0 + 8) * CS_STRIDE + cl) =
                    make_float2(acc[mi][nj][2], acc[mi][nj][3]);
            }
        }
        __syncthreads();
        const int bid = blockIdx.x * RR + group;
        const int beg = g_ofs[bid], end = g_ofs[bid + 1];
        for (int i = beg + wid; i < end; i += 8) {
            uint32_t e = g_elist[i];
            int sl = (int)(e >> 17);
            int dst = (int)(e & 0x1FFFF);
            float4 v = *(const float4*)(cs + sl * CS_STRIDE + lane * 4);
            float* p = g_Yroot + (size_t)dst * DD + nh * 128 + lane * 4;
            asm volatile("red.global.add.v4.f32 [%0], {%1, %2, %3, %4};"
                         :: "l"(p), "f"(v.x), "f"(v.y), "f"(v.z), "f"(v.w) : "memory");
        }
    }
}

// ---------------- launch ----------------
extern "C" void kernel_launch(void* const* d_in, const int* in_sizes, int n_in,
                              void* d_out, int out_size) {
    const float* x       = (const float*)d_in[0];
    const float* weights = (const float*)d_in[1];
    const float* roots   = (const float*)d_in[2];
    const float* biases  = (const float*)d_in[3];
    const void*  ei      = d_in[4];
    const void*  et      = d_in[5];

    cudaFuncSetAttribute(gemm_kernel, cudaFuncAttributeMaxDynamicSharedMemorySize, SMEM_TOTAL);

    detect_kernel<<<1, 1>>>((const int*)ei);
    conv_w_kernel<<<(3 * GG * DD * DD + 255) / 256, 256>>>(weights, roots);
    conv_x_kernel<<<(NN * DD + 255) / 256, 256>>>(x);
    zero_cnt_kernel<<<(NB + 255) / 256, 256>>>();
    count_kernel<<<(EE + 255) / 256, 256>>>(ei, et);
    scan_kernel<<<1, 1024>>>();
    fill_kernel<<<(EE + 255) / 256, 256>>>(ei, et);

    for (int l = 0; l < 3; l++) {
        const float* b = biases + (size_t)l * DD;
        // Root tiles first (plain store initializes g_Yroot)...
        gemm_kernel<<<dim3(391, 2), 256, SMEM_TOTAL>>>(b, l, 16);
        // ...then relation tiles with fused atomic scatter.
        gemm_kernel<<<dim3(391, 16), 256, SMEM_TOTAL>>>(b, l, 0);
        if (l < 2)
            act_split_kernel<<<(NN * DD + 255) / 256, 256>>>();
        else
            act_final_kernel<<<(NN * DD / 4 + 255) / 256, 256>>>((float*)d_out);
    }
}